// round 4
// baseline (speedup 1.0000x reference)
#include <cuda_runtime.h>
#include <cuda_bf16.h>
#include <cstddef>

// Problem constants: B=512, T=1024, H=128, LAT=16, COND=1, OUT=12
#define BATCH 512
#define TT    1024
#define HID   128
#define GATES 512       // 4*H
#define OUTD  12

typedef unsigned long long ull;

// Device scratch (static __device__ arrays are the sanctioned alloc-free workaround)
__device__ float g_xproj[BATCH * GATES];                      // [b][j]
__device__ float g_hs[(size_t)BATCH * TT * HID];              // [b][t][k]  (268 MB)

// ---------------- helpers ----------------
__device__ __forceinline__ ull ffma2(ull a, ull b, ull c) {
    ull d;
    asm("fma.rn.f32x2 %0, %1, %2, %3;" : "=l"(d) : "l"(a), "l"(b), "l"(c));
    return d;
}
__device__ __forceinline__ ull pack2(float lo, float hi) {
    ull d;
    asm("mov.b64 %0, {%1, %2};" : "=l"(d) : "f"(lo), "f"(hi));
    return d;
}
__device__ __forceinline__ float pairsum(ull a) {
    float lo, hi;
    asm("mov.b64 {%0, %1}, %2;" : "=f"(lo), "=f"(hi) : "l"(a));
    return lo + hi;
}
__device__ __forceinline__ float sigmoidf_(float x) {
    float e = __expf(-x);
    return __fdividef(1.f, 1.f + e);
}
__device__ __forceinline__ float tanhf_(float x) {
    float e = __expf(2.f * x);
    return 1.f - __fdividef(2.f, 1.f + e);
}

// ---------------- k1: x = latent@Ws^T + bs ; xproj = x@Wih^T + bih + bhh ----------------
// 64 blocks x 512 threads; each block handles BPB=8 batch rows; Wih row j read once per block.
#define BPB 8
__global__ __launch_bounds__(512)
void k1_xproj(const float* __restrict__ z, const float* __restrict__ c,
              const float* __restrict__ Ws, const float* __restrict__ bs,
              const float* __restrict__ Wih, const float* __restrict__ bih,
              const float* __restrict__ bhh) {
    __shared__ float sWs[HID * 17];
    __shared__ float slat[BPB * 17];
    __shared__ float sx[BPB][HID];
    const int tid = threadIdx.x;
    const int b0 = blockIdx.x * BPB;

    for (int i = tid; i < HID * 17; i += 512) sWs[i] = Ws[i];
    for (int i = tid; i < BPB * 17; i += 512) {
        int b = i / 17, q = i - b * 17;
        slat[i] = (q < 16) ? z[(b0 + b) * 16 + q] : c[b0 + b];
    }
    __syncthreads();

    // x[b][hcol], BPB*128 = 1024 entries, 512 threads -> 2 each
    for (int i = tid; i < BPB * HID; i += 512) {
        int b = i >> 7, hcol = i & 127;
        float acc = bs[hcol];
        #pragma unroll
        for (int l = 0; l < 17; l++) acc += sWs[hcol * 17 + l] * slat[b * 17 + l];
        sx[b][hcol] = acc;
    }
    __syncthreads();

    // xproj: thread j = gate row
    const int j = tid;
    float acc[BPB];
    float base = bih[j] + bhh[j];
    #pragma unroll
    for (int b = 0; b < BPB; b++) acc[b] = base;
    const float4* wr = (const float4*)(Wih + j * HID);
    #pragma unroll 4
    for (int u = 0; u < 32; u++) {
        float4 w = wr[u];
        #pragma unroll
        for (int b = 0; b < BPB; b++) {
            acc[b] += w.x * sx[b][4*u] + w.y * sx[b][4*u+1]
                    + w.z * sx[b][4*u+2] + w.w * sx[b][4*u+3];
        }
    }
    #pragma unroll
    for (int b = 0; b < BPB; b++) g_xproj[(b0 + b) * GATES + j] = acc[b];
}

// ---------------- k2: the 1024-step recurrence ----------------
// 128 CTAs x 256 threads (8 warps). CTA owns 4 batch rows.
// Warp w owns k-range [16w, 16w+16). Lane l: kl = 16w + (l&15), half = l>>4.
//   half 0: gateA = i_kl (row kl),       gateB = g_kl (row 256+kl)
//   half 1: gateA = f_kl (row 128+kl),   gateB = o_kl (row 384+kl)
// Gate-A weights in 128 registers; gate-B weights in smem (128 KB).
// Cell update is warp-local via shfl.xor(16); ONE __syncthreads per step.
// smem: wsmB [32][256] ulonglong2 (131072 B) | hbuf [2][4][128] f32 (4096 B) => 135168 B
#define K2_SMEM 135168

__global__ __launch_bounds__(256, 1)
void k2_lstm(const float* __restrict__ Whh) {
    extern __shared__ __align__(16) unsigned char sraw[];
    ulonglong2* wsmB = (ulonglong2*)sraw;                     // [u][tid]
    float* hbuf = (float*)(sraw + 131072);                    // [par][r][k]

    const int tid = threadIdx.x;
    const int w = tid >> 5;
    const int l = tid & 31;
    const int kl = w * 16 + (l & 15);
    const int half = l >> 4;                                  // 0: i/g, 1: f/o
    const int rowA = half * 128 + kl;                         // i or f
    const int rowB = 256 + half * 128 + kl;                   // g or o
    const int b0 = blockIdx.x * 4;

    // Gate-A weights -> registers (64 f32x2 pairs = 128 regs)
    ull wa[64];
    {
        const ulonglong2* rA = (const ulonglong2*)(Whh + rowA * HID);
        #pragma unroll
        for (int u = 0; u < 32; u++) {
            ulonglong2 t = rA[u];
            wa[2*u] = t.x; wa[2*u+1] = t.y;
        }
        const ulonglong2* rB = (const ulonglong2*)(Whh + rowB * HID);
        #pragma unroll
        for (int u = 0; u < 32; u++) wsmB[u * 256 + tid] = rB[u];
    }

    // Constant input projections
    float xpA[4], xpB[4];
    #pragma unroll
    for (int r = 0; r < 4; r++) {
        xpA[r] = g_xproj[(b0 + r) * GATES + rowA];
        xpB[r] = g_xproj[(b0 + r) * GATES + rowB];
    }

    // zero both h buffers
    #pragma unroll
    for (int i = 0; i < 4; i++) hbuf[tid + 256 * i] = 0.f;
    __syncthreads();

    // cell state for (r, kl), r = 0..3, kept redundantly in both warp halves
    float cc[4] = {0.f, 0.f, 0.f, 0.f};
    // store targets: half 0 stores r=0,1 ; half 1 stores r=2,3
    const int r0 = half * 2, r1 = half * 2 + 1;
    float* hs0 = g_hs + (size_t)(b0 + r0) * TT * HID + kl;
    float* hs1 = g_hs + (size_t)(b0 + r1) * TT * HID + kl;

    int par = 0;
    for (int t = 0; t < TT; t++) {
        // ---- gates = xproj + h @ Whh^T (packed f32x2) ----
        ull aA[4], aB[4];
        #pragma unroll
        for (int r = 0; r < 4; r++) { aA[r] = pack2(xpA[r], 0.f); aB[r] = pack2(xpB[r], 0.f); }
        const ulonglong2* hb = (const ulonglong2*)(hbuf + par * 512);
        #pragma unroll
        for (int u = 0; u < 32; u++) {
            ulonglong2 wb = wsmB[u * 256 + tid];
            #pragma unroll
            for (int r = 0; r < 4; r++) {
                ulonglong2 h2 = hb[r * 32 + u];          // broadcast LDS.128
                aA[r] = ffma2(wa[2*u],   h2.x, aA[r]);
                aA[r] = ffma2(wa[2*u+1], h2.y, aA[r]);
                aB[r] = ffma2(wb.x,      h2.x, aB[r]);
                aB[r] = ffma2(wb.y,      h2.y, aB[r]);
            }
        }
        // activations: gateA (i or f) -> sigmoid; gateB: g -> tanh (half0), o -> sigmoid (half1)
        float gA[4], gB[4];
        #pragma unroll
        for (int r = 0; r < 4; r++) {
            float vA = pairsum(aA[r]);
            float vB = pairsum(aB[r]);
            gA[r] = sigmoidf_(vA);
            gB[r] = (half == 0) ? tanhf_(vB) : sigmoidf_(vB);
        }
        // warp-local gate exchange: half0 <-> half1
        float shA[4], shB[4];
        #pragma unroll
        for (int r = 0; r < 4; r++) {
            shA[r] = __shfl_xor_sync(0xffffffffu, gA[r], 16);
            shB[r] = __shfl_xor_sync(0xffffffffu, gB[r], 16);
        }
        // cell update (computed redundantly by both halves; identical inputs -> identical cc)
        float hv[4];
        #pragma unroll
        for (int r = 0; r < 4; r++) {
            float iv = (half == 0) ? gA[r] : shA[r];
            float fv = (half == 0) ? shA[r] : gA[r];
            float gv = (half == 0) ? gB[r] : shB[r];
            float ov = (half == 0) ? shB[r] : gB[r];
            cc[r] = fv * cc[r] + iv * gv;
            hv[r] = ov * tanhf_(cc[r]);
        }
        // store h: each half stores its 2 rows
        float* hn = hbuf + (par ^ 1) * 512;
        hn[r0 * 128 + kl] = hv[r0];
        hn[r1 * 128 + kl] = hv[r1];
        hs0[t * HID] = hv[r0];
        hs1[t * HID] = hv[r1];
        __syncthreads();
        par ^= 1;
    }
}

// ---------------- k3: out[b,t,:] = hs[b,t,:] @ Wout^T + bout ----------------
__global__ __launch_bounds__(256)
void k3_out(const float* __restrict__ Wout, const float* __restrict__ bout,
            float* __restrict__ out) {
    __shared__ float4 wsm[OUTD][32];
    __shared__ float bo[OUTD];
    int tid = threadIdx.x;
    for (int i = tid; i < OUTD * 32; i += 256) wsm[i / 32][i % 32] = ((const float4*)Wout)[i];
    if (tid < OUTD) bo[tid] = bout[tid];
    __syncthreads();

    unsigned bt = blockIdx.x * 256 + tid;                // < 524288 exactly
    const float4* hr = (const float4*)(g_hs + (size_t)bt * HID);
    float acc[OUTD];
    #pragma unroll
    for (int o = 0; o < OUTD; o++) acc[o] = bo[o];
    #pragma unroll 4
    for (int u = 0; u < 32; u++) {
        float4 h = hr[u];
        #pragma unroll
        for (int o = 0; o < OUTD; o++) {
            float4 wv = wsm[o][u];
            acc[o] += h.x * wv.x + h.y * wv.y + h.z * wv.z + h.w * wv.w;
        }
    }
    float* op = out + (size_t)bt * OUTD;
    #pragma unroll
    for (int o = 0; o < OUTD; o++) op[o] = acc[o];
}

// ---------------- launcher ----------------
extern "C" void kernel_launch(void* const* d_in, const int* in_sizes, int n_in,
                              void* d_out, int out_size) {
    (void)in_sizes; (void)n_in; (void)out_size;
    const float* z   = (const float*)d_in[0];
    const float* c   = (const float*)d_in[1];
    const float* Ws  = (const float*)d_in[2];
    const float* bs  = (const float*)d_in[3];
    const float* Wih = (const float*)d_in[4];
    const float* bih = (const float*)d_in[5];
    const float* Whh = (const float*)d_in[6];
    const float* bhh = (const float*)d_in[7];
    const float* Wo  = (const float*)d_in[8];
    const float* bo  = (const float*)d_in[9];
    float* out = (float*)d_out;

    cudaFuncSetAttribute(k2_lstm, cudaFuncAttributeMaxDynamicSharedMemorySize, K2_SMEM);

    k1_xproj<<<BATCH / BPB, 512>>>(z, c, Ws, bs, Wih, bih, bhh);
    k2_lstm<<<128, 256, K2_SMEM>>>(Whh);
    k3_out<<<(BATCH * TT) / 256, 256>>>(Wo, bo, out);
}

// round 5
// speedup vs baseline: 1.0909x; 1.0909x over previous
#include <cuda_runtime.h>
#include <cuda_bf16.h>
#include <cstddef>

// Problem constants: B=512, T=1024, H=128, LAT=16, COND=1, OUT=12
#define BATCH 512
#define TT    1024
#define HID   128
#define GATES 512       // 4*H
#define OUTD  12

typedef unsigned long long ull;

// Device scratch (static __device__ arrays are the sanctioned alloc-free workaround)
__device__ float g_xproj[BATCH * GATES];                      // [b][j]
__device__ float g_hs[(size_t)BATCH * TT * HID];              // [b][t][k]  (268 MB)

// ---------------- helpers ----------------
__device__ __forceinline__ ull ffma2(ull a, ull b, ull c) {
    ull d;
    asm("fma.rn.f32x2 %0, %1, %2, %3;" : "=l"(d) : "l"(a), "l"(b), "l"(c));
    return d;
}
__device__ __forceinline__ ull pack2(float lo, float hi) {
    ull d;
    asm("mov.b64 %0, {%1, %2};" : "=l"(d) : "f"(lo), "f"(hi));
    return d;
}
__device__ __forceinline__ float pairsum(ull a) {
    float lo, hi;
    asm("mov.b64 {%0, %1}, %2;" : "=f"(lo), "=f"(hi) : "l"(a));
    return lo + hi;
}
__device__ __forceinline__ float sigmoidf_(float x) {
    float e = __expf(-x);
    return __fdividef(1.f, 1.f + e);
}
__device__ __forceinline__ float tanhf_(float x) {
    float e = __expf(2.f * x);
    return 1.f - __fdividef(2.f, 1.f + e);
}

// ---------------- k1: x = latent@Ws^T + bs ; xproj = x@Wih^T + bih + bhh ----------------
// 128 blocks x 512 threads; each block handles BPB=4 batch rows.
#define BPB 4
__global__ __launch_bounds__(512)
void k1_xproj(const float* __restrict__ z, const float* __restrict__ c,
              const float* __restrict__ Ws, const float* __restrict__ bs,
              const float* __restrict__ Wih, const float* __restrict__ bih,
              const float* __restrict__ bhh) {
    __shared__ float sWs[HID * 17];
    __shared__ float slat[BPB * 17];
    __shared__ float sx[BPB][HID];
    const int tid = threadIdx.x;
    const int b0 = blockIdx.x * BPB;

    for (int i = tid; i < HID * 17; i += 512) sWs[i] = Ws[i];
    if (tid < BPB * 17) {
        int b = tid / 17, q = tid - b * 17;
        slat[tid] = (q < 16) ? z[(b0 + b) * 16 + q] : c[b0 + b];
    }
    __syncthreads();

    // x[b][hcol]: 4*128 = 512 entries, 1 per thread
    {
        int b = tid >> 7, hcol = tid & 127;
        float acc = bs[hcol];
        #pragma unroll
        for (int l = 0; l < 17; l++) acc += sWs[hcol * 17 + l] * slat[b * 17 + l];
        sx[b][hcol] = acc;
    }
    __syncthreads();

    // xproj: thread j = gate row
    const int j = tid;
    float acc[BPB];
    float base = bih[j] + bhh[j];
    #pragma unroll
    for (int b = 0; b < BPB; b++) acc[b] = base;
    const float4* wr = (const float4*)(Wih + j * HID);
    #pragma unroll 8
    for (int u = 0; u < 32; u++) {
        float4 w = wr[u];
        #pragma unroll
        for (int b = 0; b < BPB; b++) {
            acc[b] += w.x * sx[b][4*u] + w.y * sx[b][4*u+1]
                    + w.z * sx[b][4*u+2] + w.w * sx[b][4*u+3];
        }
    }
    #pragma unroll
    for (int b = 0; b < BPB; b++) g_xproj[(b0 + b) * GATES + j] = acc[b];
}

// ---------------- k2: the 1024-step recurrence ----------------
// 128 CTAs x 256 threads. CTA owns 4 batch rows. Thread j owns gates j and j+256.
// Gate-A (j): all 128 weights in registers.
// Gate-B (j+256): first 32 weights (u<8) in registers, rest (u=8..31) in smem.
// Two-phase step with gbuf exchange (round-3 structure; fastest so far).
// smem: wsmB [24][256] ulonglong2 (98304 B) | hbuf [2][4][128] f32 (4096 B)
//       | gbuf [4][512] f32 (8192 B)  => 110592 B
#define K2_SMEM 110592

__global__ __launch_bounds__(256, 1)
void k2_lstm(const float* __restrict__ Whh) {
    extern __shared__ __align__(16) unsigned char sraw[];
    ulonglong2* wsmB = (ulonglong2*)sraw;                     // [u-8][tid]
    float* hbuf = (float*)(sraw + 98304);                     // [par][r][k]
    float* gbuf = (float*)(sraw + 98304 + 4096);              // [r][j]

    const int tid = threadIdx.x;
    const int b0 = blockIdx.x * 4;

    // Gate-A weights -> registers (64 f32x2 pairs = 128 regs)
    ull wa[64];
    {
        const ulonglong2* rowA = (const ulonglong2*)(Whh + tid * HID);
        #pragma unroll
        for (int u = 0; u < 32; u++) {
            ulonglong2 t = rowA[u];
            wa[2*u] = t.x; wa[2*u+1] = t.y;
        }
    }
    // Gate-B weights: u<8 -> registers (16 pairs = 32 regs), u>=8 -> smem
    ull wbr[16];
    {
        const ulonglong2* rowB = (const ulonglong2*)(Whh + (tid + 256) * HID);
        #pragma unroll
        for (int u = 0; u < 8; u++) {
            ulonglong2 t = rowB[u];
            wbr[2*u] = t.x; wbr[2*u+1] = t.y;
        }
        #pragma unroll
        for (int u = 8; u < 32; u++) wsmB[(u - 8) * 256 + tid] = rowB[u];
    }

    // Constant input projection for this thread's two gates, 4 rows
    float xpA[4], xpB[4];
    #pragma unroll
    for (int r = 0; r < 4; r++) {
        xpA[r] = g_xproj[(b0 + r) * GATES + tid];
        xpB[r] = g_xproj[(b0 + r) * GATES + 256 + tid];
    }

    // zero both h buffers
    #pragma unroll
    for (int i = 0; i < 4; i++) hbuf[tid + 256 * i] = 0.f;
    __syncthreads();

    // phase-B ownership: cells (rlo, kk) and (rlo+2, kk)
    const int kk = tid & 127;
    const int rlo = tid >> 7;   // 0 or 1
    float cA = 0.f, cB = 0.f;
    float* hsA = g_hs + (size_t)(b0 + rlo) * TT * HID + kk;
    float* hsB = g_hs + (size_t)(b0 + rlo + 2) * TT * HID + kk;
    const bool isg = (tid < 128);   // gate-b is 'g' (tanh) for j<128, else 'o' (sigmoid)

    int par = 0;
    for (int t = 0; t < TT; t++) {
        // ---- phase A: gates = xproj + h @ Whh^T ----
        ull a0[4], a1[4];
        #pragma unroll
        for (int r = 0; r < 4; r++) { a0[r] = pack2(xpA[r], 0.f); a1[r] = pack2(xpB[r], 0.f); }
        const ulonglong2* hb = (const ulonglong2*)(hbuf + par * 512);
        #pragma unroll
        for (int u = 0; u < 8; u++) {
            #pragma unroll
            for (int r = 0; r < 4; r++) {
                ulonglong2 h2 = hb[r * 32 + u];          // broadcast LDS.128
                a0[r] = ffma2(wa[2*u],    h2.x, a0[r]);
                a0[r] = ffma2(wa[2*u+1],  h2.y, a0[r]);
                a1[r] = ffma2(wbr[2*u],   h2.x, a1[r]);
                a1[r] = ffma2(wbr[2*u+1], h2.y, a1[r]);
            }
        }
        #pragma unroll
        for (int u = 8; u < 32; u++) {
            ulonglong2 wb = wsmB[(u - 8) * 256 + tid];
            #pragma unroll
            for (int r = 0; r < 4; r++) {
                ulonglong2 h2 = hb[r * 32 + u];          // broadcast LDS.128
                a0[r] = ffma2(wa[2*u],   h2.x, a0[r]);
                a0[r] = ffma2(wa[2*u+1], h2.y, a0[r]);
                a1[r] = ffma2(wb.x,      h2.x, a1[r]);
                a1[r] = ffma2(wb.y,      h2.y, a1[r]);
            }
        }
        #pragma unroll
        for (int r = 0; r < 4; r++) {
            float gA = pairsum(a0[r]);                   // gate i or f -> sigmoid
            float gB = pairsum(a1[r]);                   // gate g -> tanh, o -> sigmoid
            gbuf[r * 512 + tid]       = sigmoidf_(gA);
            gbuf[r * 512 + 256 + tid] = isg ? tanhf_(gB) : sigmoidf_(gB);
        }
        __syncthreads();

        // ---- phase B: cell update for 2 cells ----
        {
            const float* gb0 = gbuf + rlo * 512;
            float i0 = gb0[kk], f0 = gb0[128 + kk], g0 = gb0[256 + kk], o0 = gb0[384 + kk];
            const float* gb1 = gbuf + (rlo + 2) * 512;
            float i1 = gb1[kk], f1 = gb1[128 + kk], g1 = gb1[256 + kk], o1 = gb1[384 + kk];

            cA = f0 * cA + i0 * g0;
            cB = f1 * cB + i1 * g1;
            float hA = o0 * tanhf_(cA);
            float hB = o1 * tanhf_(cB);

            float* hn = hbuf + (par ^ 1) * 512;
            hn[rlo * 128 + kk]       = hA;
            hn[(rlo + 2) * 128 + kk] = hB;
            hsA[t * HID] = hA;
            hsB[t * HID] = hB;
        }
        __syncthreads();
        par ^= 1;
    }
}

// ---------------- k3: out[b,t,:] = hs[b,t,:] @ Wout^T + bout ----------------
__global__ __launch_bounds__(256)
void k3_out(const float* __restrict__ Wout, const float* __restrict__ bout,
            float* __restrict__ out) {
    __shared__ float4 wsm[OUTD][32];
    __shared__ float bo[OUTD];
    int tid = threadIdx.x;
    for (int i = tid; i < OUTD * 32; i += 256) wsm[i / 32][i % 32] = ((const float4*)Wout)[i];
    if (tid < OUTD) bo[tid] = bout[tid];
    __syncthreads();

    unsigned bt = blockIdx.x * 256 + tid;                // < 524288 exactly
    const float4* hr = (const float4*)(g_hs + (size_t)bt * HID);
    float acc[OUTD];
    #pragma unroll
    for (int o = 0; o < OUTD; o++) acc[o] = bo[o];
    #pragma unroll 4
    for (int u = 0; u < 32; u++) {
        float4 h = hr[u];
        #pragma unroll
        for (int o = 0; o < OUTD; o++) {
            float4 wv = wsm[o][u];
            acc[o] += h.x * wv.x + h.y * wv.y + h.z * wv.z + h.w * wv.w;
        }
    }
    float* op = out + (size_t)bt * OUTD;
    #pragma unroll
    for (int o = 0; o < OUTD; o++) op[o] = acc[o];
}

// ---------------- launcher ----------------
extern "C" void kernel_launch(void* const* d_in, const int* in_sizes, int n_in,
                              void* d_out, int out_size) {
    (void)in_sizes; (void)n_in; (void)out_size;
    const float* z   = (const float*)d_in[0];
    const float* c   = (const float*)d_in[1];
    const float* Ws  = (const float*)d_in[2];
    const float* bs  = (const float*)d_in[3];
    const float* Wih = (const float*)d_in[4];
    const float* bih = (const float*)d_in[5];
    const float* Whh = (const float*)d_in[6];
    const float* bhh = (const float*)d_in[7];
    const float* Wo  = (const float*)d_in[8];
    const float* bo  = (const float*)d_in[9];
    float* out = (float*)d_out;

    cudaFuncSetAttribute(k2_lstm, cudaFuncAttributeMaxDynamicSharedMemorySize, K2_SMEM);

    k1_xproj<<<BATCH / BPB, 512>>>(z, c, Ws, bs, Wih, bih, bhh);
    k2_lstm<<<128, 256, K2_SMEM>>>(Whh);
    k3_out<<<(BATCH * TT) / 256, 256>>>(Wo, bo, out);
}